// round 4
// baseline (speedup 1.0000x reference)
#include <cuda_runtime.h>
#include <cuda_bf16.h>

// QuantumLinear: B=4096, IN_F=1024, NQ=4, L=2, C=256 circuits.
// Closed-form <Z_q> via Heisenberg propagation (exact):
//   alpha_q = x_q + w[c,0,q], beta_q = w[c,1,q]
//   <Z0> = C1C3*(a0*C0 + a3*S0) + S1S3*(a1*S0 + a2*C0)
//   <Z1> = C3*(c0c1*C0C2 + s0s1*S0S2)
//   <Z2> = c0c1c2*C1C3 + c0s1s2*S1S3
//   <Z3> = C2*(e0*C0 + e1*S0) + S2*(e2*C0 + e3*S0)
// R3: ROWS=4 (grid 1024) for occupancy; x loads front-batched for MLP;
// launch_bounds(256,6) to keep 6 CTAs/SM resident.

static constexpr int NCIRC = 256;
static constexpr int ROWS  = 4;     // batch rows per thread

__global__ void __launch_bounds__(NCIRC, 6) qfused_kernel(
    const float4* __restrict__ x,     // (B*256) float4
    const float4* __restrict__ w4,    // (256*2) float4  = weights (256,2,4)
    float4* __restrict__ out)         // (B*256) float4
{
    const int c = threadIdx.x;                 // circuit 0..255
    const int base = (blockIdx.x * ROWS) * NCIRC + c;

    // ---- front-batch all memory loads (max MLP) ----
    const float4 w0 = w4[c * 2 + 0];           // alpha offsets
    const float4 w1 = w4[c * 2 + 1];           // beta angles
    float4 xv[ROWS];
#pragma unroll
    for (int r = 0; r < ROWS; r++)
        xv[r] = x[base + r * NCIRC];

    // ---- per-circuit coefficients (registers) ----
    float cb0, sb0, cb1, sb1, cb2, sb2, cb3, sb3;
    __sincosf(w1.x, &sb0, &cb0);
    __sincosf(w1.y, &sb1, &cb1);
    __sincosf(w1.z, &sb2, &cb2);
    __sincosf(w1.w, &sb3, &cb3);

    const float c1c2 = cb1 * cb2;
    const float s1s2 = sb1 * sb2;
    const float a0 = c1c2 * cb3, a1 = c1c2 * sb3;
    const float a2 = s1s2 * cb3, a3 = s1s2 * sb3;
    const float p0 = cb0 * cb1,  p1 = sb0 * sb1;
    const float d0 = cb0 * c1c2, d1 = cb0 * s1s2;
    const float e0 = cb0 * c1c2 * cb3;
    const float e1 = cb0 * s1s2 * sb3;
    const float e2 = sb0 * cb1 * sb2 * sb3;
    const float e3 = sb0 * sb1 * cb2 * cb3;

    // ---- compute + store per row ----
#pragma unroll
    for (int r = 0; r < ROWS; r++) {
        float S0, C0, S1, C1, S2, C2, S3, C3;
        __sincosf(xv[r].x + w0.x, &S0, &C0);
        __sincosf(xv[r].y + w0.y, &S1, &C1);
        __sincosf(xv[r].z + w0.z, &S2, &C2);
        __sincosf(xv[r].w + w0.w, &S3, &C3);

        const float C1C3 = C1 * C3;
        const float S1S3 = S1 * S3;
        const float C0C2 = C0 * C2;
        const float S0S2 = S0 * S2;

        float4 z;
        z.x = fmaf(C1C3, fmaf(a0, C0, a3 * S0), S1S3 * fmaf(a1, S0, a2 * C0));
        z.y = C3 * fmaf(p0, C0C2, p1 * S0S2);
        z.z = fmaf(d0, C1C3, d1 * S1S3);
        z.w = fmaf(C2, fmaf(e0, C0, e1 * S0), S2 * fmaf(e2, C0, e3 * S0));

        out[base + r * NCIRC] = z;
    }
}

extern "C" void kernel_launch(void* const* d_in, const int* in_sizes, int n_in,
                              void* d_out, int out_size) {
    const float* x = (const float*)d_in[0];       // (4096, 1024) f32
    const float* w = (const float*)d_in[1];       // (256, 2, 4)  f32
    float* out = (float*)d_out;                   // (4096, 1024) f32

    const int B = 4096;
    qfused_kernel<<<B / ROWS, NCIRC>>>(
        (const float4*)x, (const float4*)w, (float4*)out);
}

// round 5
// speedup vs baseline: 1.0372x; 1.0372x over previous
#include <cuda_runtime.h>
#include <cuda_bf16.h>

// QuantumLinear: B=4096, IN_F=1024, NQ=4, L=2, C=256 circuits.
// Closed-form <Z_q> via Heisenberg propagation (exact):
//   alpha_q = x_q + w[c,0,q], beta_q = w[c,1,q]
// R4: grid=512 (single wave), ROWS=8 (amortize prologue), depth-2 software
// pipeline on x-row loads to hide L2 latency inside each thread.

static constexpr int NCIRC = 256;
static constexpr int ROWS  = 8;     // batch rows per thread

__global__ void __launch_bounds__(NCIRC, 5) qfused_kernel(
    const float4* __restrict__ x,     // (B*256) float4
    const float4* __restrict__ w4,    // (256*2) float4  = weights (256,2,4)
    float4* __restrict__ out)         // (B*256) float4
{
    const int c = threadIdx.x;                 // circuit 0..255
    const int base = (blockIdx.x * ROWS) * NCIRC + c;

    // weight loads + first x row issued before prologue math (overlap)
    const float4 w0 = w4[c * 2 + 0];           // alpha offsets
    const float4 w1 = w4[c * 2 + 1];           // beta angles
    float4 cur = x[base];

    // ---- per-circuit coefficients (registers), overlaps cur's load latency ----
    float cb0, sb0, cb1, sb1, cb2, sb2, cb3, sb3;
    __sincosf(w1.x, &sb0, &cb0);
    __sincosf(w1.y, &sb1, &cb1);
    __sincosf(w1.z, &sb2, &cb2);
    __sincosf(w1.w, &sb3, &cb3);

    const float c1c2 = cb1 * cb2;
    const float s1s2 = sb1 * sb2;
    const float a0 = c1c2 * cb3, a1 = c1c2 * sb3;
    const float a2 = s1s2 * cb3, a3 = s1s2 * sb3;
    const float p0 = cb0 * cb1,  p1 = sb0 * sb1;
    const float d0 = cb0 * c1c2, d1 = cb0 * s1s2;
    const float e0 = cb0 * c1c2 * cb3;
    const float e1 = cb0 * s1s2 * sb3;
    const float e2 = sb0 * cb1 * sb2 * sb3;
    const float e3 = sb0 * sb1 * cb2 * cb3;

    // ---- pipelined row loop: prefetch r+1 while computing r ----
#pragma unroll
    for (int r = 0; r < ROWS; r++) {
        float4 nxt;
        if (r + 1 < ROWS) nxt = x[base + (r + 1) * NCIRC];

        float S0, C0, S1, C1, S2, C2, S3, C3;
        __sincosf(cur.x + w0.x, &S0, &C0);
        __sincosf(cur.y + w0.y, &S1, &C1);
        __sincosf(cur.z + w0.z, &S2, &C2);
        __sincosf(cur.w + w0.w, &S3, &C3);

        const float C1C3 = C1 * C3;
        const float S1S3 = S1 * S3;
        const float C0C2 = C0 * C2;
        const float S0S2 = S0 * S2;

        float4 z;
        z.x = fmaf(C1C3, fmaf(a0, C0, a3 * S0), S1S3 * fmaf(a1, S0, a2 * C0));
        z.y = C3 * fmaf(p0, C0C2, p1 * S0S2);
        z.z = fmaf(d0, C1C3, d1 * S1S3);
        z.w = fmaf(C2, fmaf(e0, C0, e1 * S0), S2 * fmaf(e2, C0, e3 * S0));

        out[base + r * NCIRC] = z;
        cur = nxt;
    }
}

extern "C" void kernel_launch(void* const* d_in, const int* in_sizes, int n_in,
                              void* d_out, int out_size) {
    const float* x = (const float*)d_in[0];       // (4096, 1024) f32
    const float* w = (const float*)d_in[1];       // (256, 2, 4)  f32
    float* out = (float*)d_out;                   // (4096, 1024) f32

    const int B = 4096;
    qfused_kernel<<<B / ROWS, NCIRC>>>(
        (const float4*)x, (const float4*)w, (float4*)out);
}